// round 1
// baseline (speedup 1.0000x reference)
#include <cuda_runtime.h>

// Problem dims (fixed by reference setup_inputs)
constexpr int B_ = 8;
constexpr int T_ = 100;
constexpr int S_ = 400;
constexpr int H_ = 256;

constexpr int TT    = 2;   // t-rows per CTA in the pass kernels
constexpr int STILE = 16;  // s-rows per SMEM tile

// Scratch (device globals — no allocation allowed)
__device__ float g_Wh[B_ * S_ * H_];    // enc @ W_h + b_attn
__device__ float g_Ws[B_ * T_ * H_];    // dec @ W_s
__device__ float g_Apre[B_ * T_ * S_];  // A_prelim
__device__ float g_cov[B_ * T_ * S_];   // shifted cumsum of A_prelim

// ---------------------------------------------------------------------------
// Accurate-enough fast tanh: tanh(x) = 1 - 2/(exp(2x)+1), via MUFU EX2 + RCP.
// Error ~1e-6; handles |x| large (exp->inf or 0) correctly.
// ---------------------------------------------------------------------------
__device__ __forceinline__ float fast_tanh(float x) {
    float e;
    asm("ex2.approx.f32 %0, %1;" : "=f"(e) : "f"(x * 2.885390081777927f)); // 2/ln2
    float r;
    asm("rcp.approx.f32 %0, %1;" : "=f"(r) : "f"(e + 1.0f));
    return fmaf(-2.0f, r, 1.0f);
}

__device__ __forceinline__ float dot_tanh4(float4 v, float4 x) {
    return v.x * fast_tanh(x.x) + v.y * fast_tanh(x.y) +
           v.z * fast_tanh(x.z) + v.w * fast_tanh(x.w);
}
__device__ __forceinline__ float4 add4(float4 a, float4 b) {
    return make_float4(a.x + b.x, a.y + b.y, a.z + b.z, a.w + b.w);
}
__device__ __forceinline__ float4 fma4(float c, float4 w, float4 x) {
    return make_float4(fmaf(c, w.x, x.x), fmaf(c, w.y, x.y),
                       fmaf(c, w.z, x.z), fmaf(c, w.w, x.w));
}

// ---------------------------------------------------------------------------
// Generic batched SGEMM, 32x32 tile, 2x2 per thread, K-chunk 16.
// C[bz] = A[bz] @ Bm[bz] (+ bias). Requires N%32==0, K%16==0; M guarded.
// ---------------------------------------------------------------------------
__global__ __launch_bounds__(256) void sgemm32(
    const float* __restrict__ A, const float* __restrict__ Bm,
    float* __restrict__ C, int M, int N, int K,
    const float* __restrict__ bias,
    long long sA, long long sB, long long sC)
{
    int bz = blockIdx.z;
    A  += (size_t)bz * sA;
    Bm += (size_t)bz * sB;
    C  += (size_t)bz * sC;

    int m0 = blockIdx.y * 32, n0 = blockIdx.x * 32;
    int tid = threadIdx.x;
    int tx = tid & 15, ty = tid >> 4;

    __shared__ float As[32][17];
    __shared__ float Bs[16][33];

    float c00 = 0.f, c01 = 0.f, c10 = 0.f, c11 = 0.f;

    for (int k = 0; k < K; k += 16) {
#pragma unroll
        for (int i = 0; i < 2; i++) {
            int e = tid + i * 256;
            int m = e >> 4, kk = e & 15;
            int gm = m0 + m;
            As[m][kk] = (gm < M) ? A[(size_t)gm * K + k + kk] : 0.f;
            int kk2 = e >> 5, n = e & 31;
            Bs[kk2][n] = Bm[(size_t)(k + kk2) * N + n0 + n];
        }
        __syncthreads();
#pragma unroll
        for (int kk = 0; kk < 16; kk++) {
            float a0 = As[ty][kk], a1 = As[ty + 16][kk];
            float b0 = Bs[kk][tx], b1 = Bs[kk][tx + 16];
            c00 = fmaf(a0, b0, c00);
            c01 = fmaf(a0, b1, c01);
            c10 = fmaf(a1, b0, c10);
            c11 = fmaf(a1, b1, c11);
        }
        __syncthreads();
    }

    float bi0 = bias ? bias[n0 + tx]      : 0.f;
    float bi1 = bias ? bias[n0 + tx + 16] : 0.f;
    if (m0 + ty < M) {
        C[(size_t)(m0 + ty) * N + n0 + tx]      = c00 + bi0;
        C[(size_t)(m0 + ty) * N + n0 + tx + 16] = c01 + bi1;
    }
    if (m0 + ty + 16 < M) {
        C[(size_t)(m0 + ty + 16) * N + n0 + tx]      = c10 + bi0;
        C[(size_t)(m0 + ty + 16) * N + n0 + tx + 16] = c11 + bi1;
    }
}

// ---------------------------------------------------------------------------
// Fused logits + softmax pass. CTA = (b, pair of t). Warps compute
// e[t,s] = clip(v . tanh(Wh[s]+Ws[t] (+cov*w_c)), +-30), mask, then softmax
// per t-row; pass2 also accumulates cov_loss.
// ---------------------------------------------------------------------------
template <bool PASS2>
__global__ __launch_bounds__(256) void attn_pass(
    const unsigned char* __restrict__ mask,
    const float* __restrict__ v,
    const float* __restrict__ wc,
    float* __restrict__ AoutParam,
    float* __restrict__ loss)
{
    __shared__ float sWh[STILE * H_];
    __shared__ float sE[TT][S_];
    __shared__ float sCov[TT][STILE];
    __shared__ float red[2][4];
    __shared__ float red2[2][4];

    int tid  = threadIdx.x;
    int lane = tid & 31, warp = tid >> 5;
    int cta  = blockIdx.x;
    int b    = cta / (T_ / TT);
    int t0   = (cta % (T_ / TT)) * TT;

    const float4* v4 = (const float4*)v;
    float4 v0 = v4[lane], v1 = v4[32 + lane];

    float4 wsr[TT][2];
#pragma unroll
    for (int j = 0; j < TT; j++) {
        const float4* w = (const float4*)(g_Ws + ((size_t)b * T_ + t0 + j) * H_);
        wsr[j][0] = w[lane];
        wsr[j][1] = w[32 + lane];
    }
    float4 wcr0 = make_float4(0, 0, 0, 0), wcr1 = wcr0;
    if (PASS2) {
        const float4* w = (const float4*)wc;
        wcr0 = w[lane];
        wcr1 = w[32 + lane];
    }

    const float* whBase = g_Wh + (size_t)b * S_ * H_;

    for (int tile = 0; tile < S_ / STILE; tile++) {
        __syncthreads();
        const float4* src = (const float4*)(whBase + (size_t)tile * STILE * H_);
        float4* dst = (float4*)sWh;
#pragma unroll
        for (int i = 0; i < 4; i++) dst[tid + 256 * i] = src[tid + 256 * i];
        if (PASS2 && tid < TT * STILE) {
            int tl = tid / STILE, sl = tid % STILE;
            sCov[tl][sl] = g_cov[((size_t)b * T_ + t0 + tl) * S_ + tile * STILE + sl];
        }
        __syncthreads();

#pragma unroll
        for (int j = 0; j < 4; j++) {
            int task = (warp << 2) | j;
            int tl = task >> 4, sl = task & 15;
            const float4* row = (const float4*)(sWh + sl * H_);
            float4 x0 = row[lane], x1 = row[32 + lane];
            float acc;
            if (PASS2) {
                float c = sCov[tl][sl];
                acc = dot_tanh4(v0, fma4(c, wcr0, add4(x0, wsr[tl][0]))) +
                      dot_tanh4(v1, fma4(c, wcr1, add4(x1, wsr[tl][1])));
            } else {
                acc = dot_tanh4(v0, add4(x0, wsr[tl][0])) +
                      dot_tanh4(v1, add4(x1, wsr[tl][1]));
            }
#pragma unroll
            for (int o = 16; o; o >>= 1) acc += __shfl_xor_sync(0xffffffffu, acc, o);
            if (lane == 0) {
                int sg = tile * STILE + sl;
                float e = fminf(fmaxf(acc, -30.0f), 30.0f);
                if (mask[b * S_ + sg]) e = -1e30f;
                sE[tl][sg] = e;
            }
        }
    }
    __syncthreads();

    // Softmax per t-row: 128 threads per row.
    int tl = tid >> 7;
    int r  = tid & 127;

    float m = -1e30f;
    for (int s = r; s < S_; s += 128) m = fmaxf(m, sE[tl][s]);
#pragma unroll
    for (int o = 16; o; o >>= 1) m = fmaxf(m, __shfl_xor_sync(0xffffffffu, m, o));
    if ((r & 31) == 0) red[tl][r >> 5] = m;
    __syncthreads();
    m = fmaxf(fmaxf(red[tl][0], red[tl][1]), fmaxf(red[tl][2], red[tl][3]));

    float sum = 0.f;
    for (int s = r; s < S_; s += 128) {
        float ex = __expf(sE[tl][s] - m);
        sE[tl][s] = ex;
        sum += ex;
    }
#pragma unroll
    for (int o = 16; o; o >>= 1) sum += __shfl_xor_sync(0xffffffffu, sum, o);
    if ((r & 31) == 0) red2[tl][r >> 5] = sum;
    __syncthreads();
    sum = red2[tl][0] + red2[tl][1] + red2[tl][2] + red2[tl][3];
    float inv = 1.0f / fmaxf(sum, 1e-30f);

    size_t rowOff = ((size_t)b * T_ + t0 + tl) * S_;
    float* Aout = (PASS2 ? AoutParam : g_Apre) + rowOff;
    float lacc = 0.f;
    for (int s = r; s < S_; s += 128) {
        float a = sE[tl][s] * inv;
        Aout[s] = a;
        if (PASS2) lacc += fminf(a, g_cov[rowOff + s]);
    }
    if (PASS2) {
#pragma unroll
        for (int o = 16; o; o >>= 1) lacc += __shfl_xor_sync(0xffffffffu, lacc, o);
        if ((r & 31) == 0) red[tl][r >> 5] = lacc;
        __syncthreads();
        if (r == 0) {
            float p = red[tl][0] + red[tl][1] + red[tl][2] + red[tl][3];
            atomicAdd(loss, p * (1.0f / (B_ * T_)));  // COV_WEIGHT=1, mean over B*T
        }
    }
}

// ---------------------------------------------------------------------------
// Shifted cumsum over t: cov[b,t,s] = sum_{t'<t} A_prelim[b,t',s].
// Also zeroes the cov_loss output slot.
// ---------------------------------------------------------------------------
__global__ void cumsum_k(float* __restrict__ loss)
{
    int idx = blockIdx.x * blockDim.x + threadIdx.x;
    if (idx == 0) *loss = 0.f;
    if (idx < B_ * S_) {
        int b = idx / S_, s = idx % S_;
        size_t base = (size_t)b * T_ * S_ + s;
        float run = 0.f;
        for (int t = 0; t < T_; t++) {
            g_cov[base + (size_t)t * S_] = run;
            run += g_Apre[base + (size_t)t * S_];
        }
    }
}

// ---------------------------------------------------------------------------
extern "C" void kernel_launch(void* const* d_in, const int* in_sizes, int n_in,
                              void* d_out, int out_size)
{
    const float*         dec    = (const float*)d_in[0];  // [B,T,H]
    const float*         enc    = (const float*)d_in[1];  // [B,S,H]
    const unsigned char* mask   = (const unsigned char*)d_in[2];  // [B,S] bool
    const float*         W_h    = (const float*)d_in[3];  // [H,H]
    const float*         W_s    = (const float*)d_in[4];  // [H,H]
    const float*         w_c    = (const float*)d_in[5];  // [H]
    const float*         v      = (const float*)d_in[6];  // [H]
    const float*         b_attn = (const float*)d_in[7];  // [H]

    float* out  = (float*)d_out;
    float* ctx  = out;                              // [B,T,H]
    float* Afin = out + (size_t)B_ * T_ * H_;       // [B,T,S]
    float* loss = Afin + (size_t)B_ * T_ * S_;      // [1]

    float *pWh = nullptr, *pWs = nullptr;
    cudaGetSymbolAddress((void**)&pWh, g_Wh);
    cudaGetSymbolAddress((void**)&pWs, g_Ws);

    dim3 blk(256);

    // Wh = enc @ W_h + b_attn   (M=B*S, N=H, K=H)
    sgemm32<<<dim3(H_ / 32, (B_ * S_ + 31) / 32, 1), blk>>>(
        enc, W_h, pWh, B_ * S_, H_, H_, b_attn, 0, 0, 0);
    // Ws = dec @ W_s            (M=B*T, N=H, K=H)
    sgemm32<<<dim3(H_ / 32, (B_ * T_ + 31) / 32, 1), blk>>>(
        dec, W_s, pWs, B_ * T_, H_, H_, nullptr, 0, 0, 0);

    // Pass 1: A_prelim
    attn_pass<false><<<B_ * (T_ / TT), blk>>>(mask, v, nullptr, nullptr, nullptr);

    // Shifted cumsum over t (also zeroes loss slot)
    cumsum_k<<<(B_ * S_ + 255) / 256, blk>>>(loss);

    // Pass 2: A_final + cov_loss
    attn_pass<true><<<B_ * (T_ / TT), blk>>>(mask, v, w_c, Afin, loss);

    // context[b] = A_final[b] @ enc[b]   (M=T, N=H, K=S, batched over b)
    sgemm32<<<dim3(H_ / 32, (T_ + 31) / 32, B_), blk>>>(
        Afin, enc, ctx, T_, H_, S_, nullptr,
        (long long)T_ * S_, (long long)S_ * H_, (long long)T_ * H_);
}

// round 2
// speedup vs baseline: 1.4349x; 1.4349x over previous
#include <cuda_runtime.h>

// Problem dims (fixed by reference setup_inputs)
constexpr int B_ = 8;
constexpr int T_ = 100;
constexpr int S_ = 400;
constexpr int H_ = 256;

constexpr int TT    = 2;   // t-rows per CTA in the pass kernels
constexpr int STILE = 16;  // s-rows per SMEM tile

// Scratch (device globals — no allocation allowed)
__device__ float g_Wh[B_ * S_ * H_];    // enc @ W_h + b_attn
__device__ float g_Ws[B_ * T_ * H_];    // dec @ W_s
__device__ float g_Apre[B_ * T_ * S_];  // A_prelim
__device__ float g_cov[B_ * T_ * S_];   // shifted cumsum of A_prelim

// ---------------------------------------------------------------------------
// Single-MUFU tanh (sm_75+ tanh.approx). Abs err ~5e-4, fine for 1e-3 budget.
// ---------------------------------------------------------------------------
__device__ __forceinline__ float fast_tanh(float x) {
    float y;
    asm("tanh.approx.f32 %0, %1;" : "=f"(y) : "f"(x));
    return y;
}

__device__ __forceinline__ float dot_tanh4(float4 v, float4 x) {
    return v.x * fast_tanh(x.x) + v.y * fast_tanh(x.y) +
           v.z * fast_tanh(x.z) + v.w * fast_tanh(x.w);
}
__device__ __forceinline__ float4 add4(float4 a, float4 b) {
    return make_float4(a.x + b.x, a.y + b.y, a.z + b.z, a.w + b.w);
}
__device__ __forceinline__ float4 fma4(float c, float4 w, float4 x) {
    return make_float4(fmaf(c, w.x, x.x), fmaf(c, w.y, x.y),
                       fmaf(c, w.z, x.z), fmaf(c, w.w, x.w));
}

// ---------------------------------------------------------------------------
// 64x64-tile SGEMM, 256 threads, 4x4 per thread, K-chunk 16.
// C = A @ Bm (+bias broadcast over rows). N%64==0, K%16==0; M guarded.
// ---------------------------------------------------------------------------
__global__ __launch_bounds__(256) void sgemm64(
    const float* __restrict__ A, const float* __restrict__ Bm,
    float* __restrict__ C, int M, int N, int K,
    const float* __restrict__ bias)
{
    int m0 = blockIdx.y * 64, n0 = blockIdx.x * 64;
    int tid = threadIdx.x;
    int tx = tid & 15, ty = tid >> 4;

    __shared__ float As[16][68];  // [k][m]
    __shared__ float Bs[16][68];  // [k][n]

    float acc[4][4] = {};

    int lm  = tid >> 2;  // 0..63 : A row within tile
    int lk4 = tid & 3;   // float4 index within 16-wide k chunk
    int bkr = tid >> 4;  // 0..15 : B k-row
    int bnc = tid & 15;  // B col group

    for (int k = 0; k < K; k += 16) {
        float4 av = make_float4(0.f, 0.f, 0.f, 0.f);
        int gm = m0 + lm;
        if (gm < M) av = *(const float4*)(A + (size_t)gm * K + k + lk4 * 4);
        As[lk4 * 4 + 0][lm] = av.x;
        As[lk4 * 4 + 1][lm] = av.y;
        As[lk4 * 4 + 2][lm] = av.z;
        As[lk4 * 4 + 3][lm] = av.w;
        float4 bv = *(const float4*)(Bm + (size_t)(k + bkr) * N + n0 + bnc * 4);
        *(float4*)&Bs[bkr][bnc * 4] = bv;
        __syncthreads();
#pragma unroll
        for (int kk = 0; kk < 16; kk++) {
            float4 a = *(float4*)&As[kk][ty * 4];
            float4 b = *(float4*)&Bs[kk][tx * 4];
            acc[0][0] = fmaf(a.x, b.x, acc[0][0]);
            acc[0][1] = fmaf(a.x, b.y, acc[0][1]);
            acc[0][2] = fmaf(a.x, b.z, acc[0][2]);
            acc[0][3] = fmaf(a.x, b.w, acc[0][3]);
            acc[1][0] = fmaf(a.y, b.x, acc[1][0]);
            acc[1][1] = fmaf(a.y, b.y, acc[1][1]);
            acc[1][2] = fmaf(a.y, b.z, acc[1][2]);
            acc[1][3] = fmaf(a.y, b.w, acc[1][3]);
            acc[2][0] = fmaf(a.z, b.x, acc[2][0]);
            acc[2][1] = fmaf(a.z, b.y, acc[2][1]);
            acc[2][2] = fmaf(a.z, b.z, acc[2][2]);
            acc[2][3] = fmaf(a.z, b.w, acc[2][3]);
            acc[3][0] = fmaf(a.w, b.x, acc[3][0]);
            acc[3][1] = fmaf(a.w, b.y, acc[3][1]);
            acc[3][2] = fmaf(a.w, b.z, acc[3][2]);
            acc[3][3] = fmaf(a.w, b.w, acc[3][3]);
        }
        __syncthreads();
    }

#pragma unroll
    for (int i = 0; i < 4; i++) {
        int gm = m0 + ty * 4 + i;
        if (gm < M) {
#pragma unroll
            for (int j = 0; j < 4; j++) {
                int gn = n0 + tx * 4 + j;
                float bi = bias ? bias[gn] : 0.f;
                C[(size_t)gm * N + gn] = acc[i][j] + bi;
            }
        }
    }
}

// ---------------------------------------------------------------------------
// Batched SGEMM, 32x32 tile, 2x2 per thread, K-chunk 16 (small matrices).
// ---------------------------------------------------------------------------
__global__ __launch_bounds__(256) void sgemm32(
    const float* __restrict__ A, const float* __restrict__ Bm,
    float* __restrict__ C, int M, int N, int K,
    const float* __restrict__ bias,
    long long sA, long long sB, long long sC)
{
    int bz = blockIdx.z;
    A  += (size_t)bz * sA;
    Bm += (size_t)bz * sB;
    C  += (size_t)bz * sC;

    int m0 = blockIdx.y * 32, n0 = blockIdx.x * 32;
    int tid = threadIdx.x;
    int tx = tid & 15, ty = tid >> 4;

    __shared__ float As[32][17];
    __shared__ float Bs[16][33];

    float c00 = 0.f, c01 = 0.f, c10 = 0.f, c11 = 0.f;

    for (int k = 0; k < K; k += 16) {
#pragma unroll
        for (int i = 0; i < 2; i++) {
            int e = tid + i * 256;
            int m = e >> 4, kk = e & 15;
            int gm = m0 + m;
            As[m][kk] = (gm < M) ? A[(size_t)gm * K + k + kk] : 0.f;
            int kk2 = e >> 5, n = e & 31;
            Bs[kk2][n] = Bm[(size_t)(k + kk2) * N + n0 + n];
        }
        __syncthreads();
#pragma unroll
        for (int kk = 0; kk < 16; kk++) {
            float a0 = As[ty][kk], a1 = As[ty + 16][kk];
            float b0 = Bs[kk][tx], b1 = Bs[kk][tx + 16];
            c00 = fmaf(a0, b0, c00);
            c01 = fmaf(a0, b1, c01);
            c10 = fmaf(a1, b0, c10);
            c11 = fmaf(a1, b1, c11);
        }
        __syncthreads();
    }

    float bi0 = bias ? bias[n0 + tx]      : 0.f;
    float bi1 = bias ? bias[n0 + tx + 16] : 0.f;
    if (m0 + ty < M) {
        C[(size_t)(m0 + ty) * N + n0 + tx]      = c00 + bi0;
        C[(size_t)(m0 + ty) * N + n0 + tx + 16] = c01 + bi1;
    }
    if (m0 + ty + 16 < M) {
        C[(size_t)(m0 + ty + 16) * N + n0 + tx]      = c10 + bi0;
        C[(size_t)(m0 + ty + 16) * N + n0 + tx + 16] = c11 + bi1;
    }
}

// ---------------------------------------------------------------------------
// Fused logits + softmax pass. CTA = (b, pair of t).
// ---------------------------------------------------------------------------
template <bool PASS2>
__global__ __launch_bounds__(256) void attn_pass(
    const unsigned char* __restrict__ mask,
    const float* __restrict__ v,
    const float* __restrict__ wc,
    float* __restrict__ AoutParam,
    float* __restrict__ loss)
{
    __shared__ float sWh[STILE * H_];
    __shared__ float sE[TT][S_];
    __shared__ float sCov[TT][STILE];
    __shared__ float red[2][4];
    __shared__ float red2[2][4];

    int tid  = threadIdx.x;
    int lane = tid & 31, warp = tid >> 5;
    int cta  = blockIdx.x;
    int b    = cta / (T_ / TT);
    int t0   = (cta % (T_ / TT)) * TT;

    const float4* v4 = (const float4*)v;
    float4 v0 = v4[lane], v1 = v4[32 + lane];

    float4 wsr[TT][2];
#pragma unroll
    for (int j = 0; j < TT; j++) {
        const float4* w = (const float4*)(g_Ws + ((size_t)b * T_ + t0 + j) * H_);
        wsr[j][0] = w[lane];
        wsr[j][1] = w[32 + lane];
    }
    float4 wcr0 = make_float4(0, 0, 0, 0), wcr1 = wcr0;
    if (PASS2) {
        const float4* w = (const float4*)wc;
        wcr0 = w[lane];
        wcr1 = w[32 + lane];
    }

    const float* whBase = g_Wh + (size_t)b * S_ * H_;

    for (int tile = 0; tile < S_ / STILE; tile++) {
        __syncthreads();
        const float4* src = (const float4*)(whBase + (size_t)tile * STILE * H_);
        float4* dst = (float4*)sWh;
#pragma unroll
        for (int i = 0; i < 4; i++) dst[tid + 256 * i] = src[tid + 256 * i];
        if (PASS2 && tid < TT * STILE) {
            int tl = tid / STILE, sl = tid % STILE;
            sCov[tl][sl] = g_cov[((size_t)b * T_ + t0 + tl) * S_ + tile * STILE + sl];
        }
        __syncthreads();

#pragma unroll
        for (int j = 0; j < 4; j++) {
            int task = (warp << 2) | j;
            int tl = task >> 4, sl = task & 15;
            const float4* row = (const float4*)(sWh + sl * H_);
            float4 x0 = row[lane], x1 = row[32 + lane];
            float acc;
            if (PASS2) {
                float c = sCov[tl][sl];
                acc = dot_tanh4(v0, fma4(c, wcr0, add4(x0, wsr[tl][0]))) +
                      dot_tanh4(v1, fma4(c, wcr1, add4(x1, wsr[tl][1])));
            } else {
                acc = dot_tanh4(v0, add4(x0, wsr[tl][0])) +
                      dot_tanh4(v1, add4(x1, wsr[tl][1]));
            }
#pragma unroll
            for (int o = 16; o; o >>= 1) acc += __shfl_xor_sync(0xffffffffu, acc, o);
            if (lane == 0) {
                int sg = tile * STILE + sl;
                float e = fminf(fmaxf(acc, -30.0f), 30.0f);
                if (mask[b * S_ + sg]) e = -1e30f;
                sE[tl][sg] = e;
            }
        }
    }
    __syncthreads();

    // Softmax per t-row: 128 threads per row.
    int tl = tid >> 7;
    int r  = tid & 127;

    float m = -1e30f;
    for (int s = r; s < S_; s += 128) m = fmaxf(m, sE[tl][s]);
#pragma unroll
    for (int o = 16; o; o >>= 1) m = fmaxf(m, __shfl_xor_sync(0xffffffffu, m, o));
    if ((r & 31) == 0) red[tl][r >> 5] = m;
    __syncthreads();
    m = fmaxf(fmaxf(red[tl][0], red[tl][1]), fmaxf(red[tl][2], red[tl][3]));

    float sum = 0.f;
    for (int s = r; s < S_; s += 128) {
        float ex = __expf(sE[tl][s] - m);
        sE[tl][s] = ex;
        sum += ex;
    }
#pragma unroll
    for (int o = 16; o; o >>= 1) sum += __shfl_xor_sync(0xffffffffu, sum, o);
    if ((r & 31) == 0) red2[tl][r >> 5] = sum;
    __syncthreads();
    sum = red2[tl][0] + red2[tl][1] + red2[tl][2] + red2[tl][3];
    float inv = 1.0f / fmaxf(sum, 1e-30f);

    size_t rowOff = ((size_t)b * T_ + t0 + tl) * S_;
    float* Aout = (PASS2 ? AoutParam : g_Apre) + rowOff;
    float lacc = 0.f;
    for (int s = r; s < S_; s += 128) {
        float a = sE[tl][s] * inv;
        Aout[s] = a;
        if (PASS2) lacc += fminf(a, g_cov[rowOff + s]);
    }
    if (PASS2) {
#pragma unroll
        for (int o = 16; o; o >>= 1) lacc += __shfl_xor_sync(0xffffffffu, lacc, o);
        if ((r & 31) == 0) red[tl][r >> 5] = lacc;
        __syncthreads();
        if (r == 0) {
            float p = red[tl][0] + red[tl][1] + red[tl][2] + red[tl][3];
            atomicAdd(loss, p * (1.0f / (B_ * T_)));
        }
    }
}

// ---------------------------------------------------------------------------
// Shifted cumsum over t, MLP-batched (10 independent loads per group).
// ---------------------------------------------------------------------------
__global__ void cumsum_k(float* __restrict__ loss)
{
    int idx = blockIdx.x * blockDim.x + threadIdx.x;
    if (idx == 0) *loss = 0.f;
    if (idx < B_ * S_) {
        int b = idx / S_, s = idx % S_;
        size_t base = (size_t)b * T_ * S_ + s;
        float run = 0.f;
        for (int t0 = 0; t0 < T_; t0 += 10) {
            float vals[10];
#pragma unroll
            for (int u = 0; u < 10; u++)
                vals[u] = g_Apre[base + (size_t)(t0 + u) * S_];
#pragma unroll
            for (int u = 0; u < 10; u++) {
                g_cov[base + (size_t)(t0 + u) * S_] = run;
                run += vals[u];
            }
        }
    }
}

// ---------------------------------------------------------------------------
extern "C" void kernel_launch(void* const* d_in, const int* in_sizes, int n_in,
                              void* d_out, int out_size)
{
    const float*         dec    = (const float*)d_in[0];  // [B,T,H]
    const float*         enc    = (const float*)d_in[1];  // [B,S,H]
    const unsigned char* mask   = (const unsigned char*)d_in[2];  // [B,S] bool
    const float*         W_h    = (const float*)d_in[3];  // [H,H]
    const float*         W_s    = (const float*)d_in[4];  // [H,H]
    const float*         w_c    = (const float*)d_in[5];  // [H]
    const float*         v      = (const float*)d_in[6];  // [H]
    const float*         b_attn = (const float*)d_in[7];  // [H]

    float* out  = (float*)d_out;
    float* ctx  = out;                              // [B,T,H]
    float* Afin = out + (size_t)B_ * T_ * H_;       // [B,T,S]
    float* loss = Afin + (size_t)B_ * T_ * S_;      // [1]

    float *pWh = nullptr, *pWs = nullptr;
    cudaGetSymbolAddress((void**)&pWh, g_Wh);
    cudaGetSymbolAddress((void**)&pWs, g_Ws);

    dim3 blk(256);

    // Wh = enc @ W_h + b_attn   (M=B*S=3200, N=H, K=H) — big one, 64x64 tiles
    sgemm64<<<dim3(H_ / 64, (B_ * S_ + 63) / 64), blk>>>(
        enc, W_h, pWh, B_ * S_, H_, H_, b_attn);
    // Ws = dec @ W_s            (M=B*T=800) — 32x32 tiles for CTA count
    sgemm32<<<dim3(H_ / 32, (B_ * T_ + 31) / 32, 1), blk>>>(
        dec, W_s, pWs, B_ * T_, H_, H_, nullptr, 0, 0, 0);

    // Pass 1: A_prelim
    attn_pass<false><<<B_ * (T_ / TT), blk>>>(mask, v, nullptr, nullptr, nullptr);

    // Shifted cumsum over t (also zeroes loss slot)
    cumsum_k<<<(B_ * S_ + 255) / 256, blk>>>(loss);

    // Pass 2: A_final + cov_loss
    attn_pass<true><<<B_ * (T_ / TT), blk>>>(mask, v, w_c, Afin, loss);

    // context[b] = A_final[b] @ enc[b]   (M=T, N=H, K=S, batched over b)
    sgemm32<<<dim3(H_ / 32, (T_ + 31) / 32, B_), blk>>>(
        Afin, enc, ctx, T_, H_, S_, nullptr,
        (long long)T_ * S_, (long long)S_ * H_, (long long)T_ * H_);
}